// round 13
// baseline (speedup 1.0000x reference)
#include <cuda_runtime.h>

typedef unsigned long long u64;

#define BATCH 32
#define NSEQ  2048
#define F     32
#define SPLITS 32
#define ROWS1 64
#define INV_N (1.0f / 2048.0f)

// Scratch (fully overwritten every launch -> deterministic)
__device__ float g_Spart[BATCH * SPLITS * F * F];   // xT @ u partials
__device__ float g_supart[BATCH * SPLITS * F];      // colsum(u) partials
__device__ float g_uwT[BATCH * F * NSEQ];           // (u @ w_r) transposed
__device__ float g_M3[BATCH * F * F];               // W_psi @ (M @ w_r * invN)
__device__ float g_b3[BATCH * F];                   // b_psi @ (M @ w_r * invN)
__device__ float g_G[F * F];                        // W_psi @ W_phi^T
__device__ float g_v[F];                            // W_psi@b_phi + W_phi@b_psi
__device__ float g_c[1];                            // b_psi . b_phi

// ---- packed f32x2 helpers ----
__device__ __forceinline__ u64 pk2(float a, float b) {
    u64 r; asm("mov.b64 %0,{%1,%2};" : "=l"(r) : "f"(a), "f"(b)); return r;
}
__device__ __forceinline__ float2 up2(u64 v) {
    float2 f; asm("mov.b64 {%0,%1},%2;" : "=f"(f.x), "=f"(f.y) : "l"(v)); return f;
}
__device__ __forceinline__ u64 ffma2(u64 a, u64 b, u64 c) {
    u64 d; asm("fma.rn.f32x2 %0,%1,%2,%3;" : "=l"(d) : "l"(a), "l"(b), "l"(c)); return d;
}
__device__ __forceinline__ u64 add2(u64 a, u64 b) {
    u64 d; asm("add.rn.f32x2 %0,%1,%2;" : "=l"(d) : "l"(a), "l"(b)); return d;
}

// ---------------------------------------------------------------------------
// k_pre: G = W_psi @ W_phi^T, v = W_psi@b_phi + W_phi@b_psi, c = b_psi.b_phi
// ---------------------------------------------------------------------------
__global__ __launch_bounds__(256) void k_pre(
    const float* __restrict__ w_psi, const float* __restrict__ b_psi,
    const float* __restrict__ w_phi, const float* __restrict__ b_phi)
{
    __shared__ alignas(16) float wps[F * F], wfs[F * F];
    __shared__ float bps[F], bfs[F];
    const int t = threadIdx.x;

    ((float4*)wps)[t] = ((const float4*)w_psi)[t];
    ((float4*)wfs)[t] = ((const float4*)w_phi)[t];
    if (t < F) { bps[t] = b_psi[t]; bfs[t] = b_phi[t]; }
    __syncthreads();

    const int k1 = t >> 3;
    const int c0 = (t & 7) * 4;
    float a0 = 0.f, a1 = 0.f, a2 = 0.f, a3 = 0.f;
#pragma unroll
    for (int f = 0; f < F; f++) {
        const float pw = wps[k1 * F + f];
        a0 += pw * wfs[(c0 + 0) * F + f];
        a1 += pw * wfs[(c0 + 1) * F + f];
        a2 += pw * wfs[(c0 + 2) * F + f];
        a3 += pw * wfs[(c0 + 3) * F + f];
    }
    *(float4*)(g_G + k1 * F + c0) = make_float4(a0, a1, a2, a3);

    if (t < F) {
        float s = 0.f;
#pragma unroll
        for (int f = 0; f < F; f++)
            s += wps[t * F + f] * bfs[f] + wfs[t * F + f] * bps[f];
        g_v[t] = s;
    }
    if (t == 0) {
        float s = 0.f;
#pragma unroll
        for (int f = 0; f < F; f++) s += bps[f] * bfs[f];
        g_c[0] = s;
    }
}

// ---------------------------------------------------------------------------
// k1: per 64-row slice (2 thr/row, 16 feats):
//   u = relu(x@Wu + bu); uw = u@w_r (persist transposed);
//   S_part = x^T @ u; su_part = colsum(u).
// ---------------------------------------------------------------------------
__global__ __launch_bounds__(128) void k1(
    const float* __restrict__ x,
    const float* __restrict__ w_u, const float* __restrict__ b_u,
    const float* __restrict__ w_r)
{
    __shared__ alignas(16) float ws_u[F * F], ws_r[F * F];
    __shared__ alignas(16) float bs_u[F];
    __shared__ alignas(16) float x36[ROWS1 * 36];   // row-major, uniform .128 reads
    __shared__ alignas(16) float u33[ROWS1 * 33];   // conflict-free row AND column

    const int b     = blockIdx.x;
    const int split = blockIdx.y;
    const int t     = threadIdx.x;
    const int r     = t & 63;
    const int h     = t >> 6;
    const int lane  = t & 31;
    const int w     = t >> 5;
    const int hoff  = h * 16;

#pragma unroll
    for (int i = t; i < 256; i += 128) {
        ((float4*)ws_u)[i] = ((const float4*)w_u)[i];
        ((float4*)ws_r)[i] = ((const float4*)w_r)[i];
    }
    if (t < F) bs_u[t] = b_u[t];

    const int row_in_b = split * ROWS1 + r;
    const float* xrow = x + ((size_t)b * NSEQ + row_in_b) * F;

    float xv[F];
#pragma unroll
    for (int i = 0; i < 8; i++) {
        float4 v = ((const float4*)xrow)[i];
        xv[4*i+0] = v.x; xv[4*i+1] = v.y; xv[4*i+2] = v.z; xv[4*i+3] = v.w;
    }
    u64 xp[8];   // this thread's half of the row, packed
#pragma unroll
    for (int i = 0; i < 8; i++) xp[i] = ((const u64*)(xrow + hoff))[i];
    __syncthreads();

    // ---- u = relu(x@Wu + bu), 16 feats ----
    u64 uv[8];
#pragma unroll
    for (int i = 0; i < 8; i++) uv[i] = ((const u64*)bs_u)[h * 8 + i];
#pragma unroll
    for (int k = 0; k < F; k++) {
        const u64 xk2 = pk2(xv[k], xv[k]);
        const ulonglong2* wu = (const ulonglong2*)(ws_u + k * F + hoff);
#pragma unroll
        for (int q = 0; q < 4; q++) {
            ulonglong2 a = wu[q];
            uv[2*q+0] = ffma2(xk2, a.x, uv[2*q+0]);
            uv[2*q+1] = ffma2(xk2, a.y, uv[2*q+1]);
        }
    }
#pragma unroll
    for (int i = 0; i < 8; i++) {
        float2 tu = up2(uv[i]);
        uv[i] = pk2(fmaxf(tu.x, 0.0f), fmaxf(tu.y, 0.0f));
    }

    // ---- stage u (stride 33) and x (stride 36) ----
#pragma unroll
    for (int i = 0; i < 8; i++) {
        float2 tu = up2(uv[i]);
        u33[r * 33 + hoff + 2*i + 0] = tu.x;
        u33[r * 33 + hoff + 2*i + 1] = tu.y;
    }
#pragma unroll
    for (int q = 0; q < 4; q++) {
        ulonglong2 v; v.x = xp[2*q]; v.y = xp[2*q+1];
        ((ulonglong2*)(x36 + r * 36 + hoff))[q] = v;
    }
    __syncthreads();

    // ---- uw = u @ w_r (16 feats), persist transposed ----
    u64 uw[8] = {0,0,0,0,0,0,0,0};
#pragma unroll
    for (int f = 0; f < F; f++) {
        const float uf = u33[r * 33 + f];
        const u64 uf2 = pk2(uf, uf);
        const ulonglong2* wr = (const ulonglong2*)(ws_r + f * F + hoff);
#pragma unroll
        for (int q = 0; q < 4; q++) {
            ulonglong2 a = wr[q];
            uw[2*q+0] = ffma2(uf2, a.x, uw[2*q+0]);
            uw[2*q+1] = ffma2(uf2, a.y, uw[2*q+1]);
        }
    }
#pragma unroll
    for (int i = 0; i < 8; i++) {
        float2 v = up2(uw[i]);
        g_uwT[((size_t)b * F + hoff + 2*i + 0) * NSEQ + row_in_b] = v.x;
        g_uwT[((size_t)b * F + hoff + 2*i + 1) * NSEQ + row_in_b] = v.y;
    }

    // ---- S_part[k][f2] = sum_j x[j][k]*u[j][f2]; su_part[f2] = sum_j u[j][f2]
    //      warp w owns k in [8w,8w+8), lane = f2.
    u64 acc2[4] = {0,0,0,0};
    float susum = 0.0f;
#pragma unroll 4
    for (int j = 0; j < ROWS1; j++) {
        const float uj = u33[j * 33 + lane];            // conflict-free
        const u64 uj2 = pk2(uj, uj);
        const ulonglong2* xr2 = (const ulonglong2*)(x36 + j * 36 + w * 8);
        ulonglong2 p0 = xr2[0], p1 = xr2[1];            // uniform .128
        acc2[0] = ffma2(uj2, p0.x, acc2[0]);
        acc2[1] = ffma2(uj2, p0.y, acc2[1]);
        acc2[2] = ffma2(uj2, p1.x, acc2[2]);
        acc2[3] = ffma2(uj2, p1.y, acc2[3]);
        susum += uj;
    }
    float* sp = g_Spart + ((size_t)(b * SPLITS + split)) * F * F;
#pragma unroll
    for (int q = 0; q < 4; q++) {
        float2 v = up2(acc2[q]);
        sp[(8*w + 2*q + 0) * F + lane] = v.x;
        sp[(8*w + 2*q + 1) * F + lane] = v.y;
    }
    if (w == 0)
        g_supart[(b * SPLITS + split) * F + lane] = susum;
}

// ---------------------------------------------------------------------------
// k_reduceM: S = sum partials; su = sum; M = Wphi^T S + bphi (x) su;
//            M2 = M@wr*invN; M3 = Wpsi@M2 -> global; b3 = bpsi@M2 -> global
// ---------------------------------------------------------------------------
__global__ __launch_bounds__(256) void k_reduceM(
    const float* __restrict__ w_phi, const float* __restrict__ b_phi,
    const float* __restrict__ w_r,
    const float* __restrict__ w_psi, const float* __restrict__ b_psi)
{
    __shared__ alignas(16) float Ss[F * F], wfs[F * F], wrs[F * F], wps[F * F];
    __shared__ alignas(16) float Ms[F * F], m2s[F * F];
    __shared__ alignas(16) float sus[F], bfs[F], bps[F];
    const int b = blockIdx.x;
    const int t = threadIdx.x;

#pragma unroll
    for (int e = t; e < F * F; e += 256) {
        float s = 0.0f;
        const float* sp = g_Spart + (size_t)b * SPLITS * F * F + e;
#pragma unroll
        for (int q = 0; q < SPLITS; q++) s += sp[q * F * F];
        Ss[e]  = s;
        wfs[e] = w_phi[e];
        wrs[e] = w_r[e];
        wps[e] = w_psi[e];
    }
    if (t < F) {
        float s = 0.0f;
        const float* up = g_supart + (size_t)b * SPLITS * F + t;
#pragma unroll
        for (int q = 0; q < SPLITS; q++) s += up[q * F];
        sus[t] = s;
        bfs[t] = b_phi[t];
        bps[t] = b_psi[t];
    }
    __syncthreads();

    const int f1 = t >> 3;
    const int c0 = (t & 7) * 4;
    {   // M[f1][c0..] = sum_m Wphi[m][f1]*S[m][c0..] + bphi[f1]*su[c0..]
        float4 su4 = *(const float4*)(sus + c0);
        const float bf = bfs[f1];
        float a0 = bf * su4.x, a1 = bf * su4.y, a2 = bf * su4.z, a3 = bf * su4.w;
#pragma unroll
        for (int m = 0; m < F; m++) {
            const float wv = wfs[m * F + f1];
            float4 s4 = *(const float4*)(Ss + m * F + c0);
            a0 += wv * s4.x; a1 += wv * s4.y; a2 += wv * s4.z; a3 += wv * s4.w;
        }
        *(float4*)(Ms + f1 * F + c0) = make_float4(a0, a1, a2, a3);
    }
    __syncthreads();
    {   // M2 = M @ wr * invN
        float a0 = 0.f, a1 = 0.f, a2 = 0.f, a3 = 0.f;
#pragma unroll
        for (int m = 0; m < F; m++) {
            const float mv = Ms[f1 * F + m];
            float4 w4 = *(const float4*)(wrs + m * F + c0);
            a0 += mv * w4.x; a1 += mv * w4.y; a2 += mv * w4.z; a3 += mv * w4.w;
        }
        *(float4*)(m2s + f1 * F + c0) =
            make_float4(a0 * INV_N, a1 * INV_N, a2 * INV_N, a3 * INV_N);
    }
    __syncthreads();
    {   // M3 = Wpsi @ M2
        float a0 = 0.f, a1 = 0.f, a2 = 0.f, a3 = 0.f;
#pragma unroll
        for (int m = 0; m < F; m++) {
            const float wv = wps[f1 * F + m];
            float4 m4 = *(const float4*)(m2s + m * F + c0);
            a0 += wv * m4.x; a1 += wv * m4.y; a2 += wv * m4.z; a3 += wv * m4.w;
        }
        *(float4*)(g_M3 + (size_t)b * F * F + f1 * F + c0) =
            make_float4(a0, a1, a2, a3);
    }
    if (t < 8) {   // b3 = bpsi @ M2
        const int f = t * 4;
        float a0 = 0.f, a1 = 0.f, a2 = 0.f, a3 = 0.f;
#pragma unroll
        for (int m = 0; m < F; m++) {
            const float bv = bps[m];
            float4 m4 = *(const float4*)(m2s + m * F + f);
            a0 += bv * m4.x; a1 += bv * m4.y; a2 += bv * m4.z; a3 += bv * m4.w;
        }
        *(float4*)(g_b3 + (size_t)b * F + f) = make_float4(a0, a1, a2, a3);
    }
}

// ---------------------------------------------------------------------------
// k_main: 2 thr/row, 64 rows, fused x@M3 + x@G loop, x in registers.
//   diag = x@G.x + x.v + c;  out = x + x@M3 + b3 - (diag/N)*uw
// ---------------------------------------------------------------------------
__global__ __launch_bounds__(128) void k_main(
    const float* __restrict__ x, float* __restrict__ out)
{
    __shared__ alignas(16) float Gs[F * F], m3s[F * F];
    __shared__ alignas(16) float vs[F], b3s[F];
    __shared__ float ds[2][64];
    __shared__ float cs1;

    const int b     = blockIdx.x >> 5;
    const int chunk = blockIdx.x & 31;
    const int t     = threadIdx.x;
    const int r     = t & 63;
    const int h     = t >> 6;
    const int hoff  = h * 16;

#pragma unroll
    for (int i = t; i < 256; i += 128) {
        ((float4*)Gs )[i] = ((const float4*)g_G)[i];
        ((float4*)m3s)[i] = ((const float4*)(g_M3 + (size_t)b * F * F))[i];
    }
    if (t < F) { vs[t] = g_v[t]; b3s[t] = g_b3[(size_t)b * F + t]; }
    if (t == 0) cs1 = g_c[0];

    const int row_in_b = chunk * 64 + r;
    const size_t gx = ((size_t)b * NSEQ + row_in_b) * F;

    float xv[F];
#pragma unroll
    for (int i = 0; i < 8; i++) {
        float4 v = ((const float4*)(x + gx))[i];
        xv[4*i+0] = v.x; xv[4*i+1] = v.y; xv[4*i+2] = v.z; xv[4*i+3] = v.w;
    }
    u64 xp[8];
#pragma unroll
    for (int i = 0; i < 8; i++) xp[i] = ((const u64*)(x + gx + hoff))[i];
    __syncthreads();

    // ---- fused: o = b3 + x@M3 ; tt = x@G (both over this half's 16 feats)
    u64 o[8], tt[8];
#pragma unroll
    for (int i = 0; i < 8; i++) { o[i] = ((const u64*)b3s)[h * 8 + i]; tt[i] = 0ull; }
#pragma unroll
    for (int k = 0; k < F; k++) {
        const u64 xk2 = pk2(xv[k], xv[k]);
        const ulonglong2* mr = (const ulonglong2*)(m3s + k * F + hoff);
        const ulonglong2* gr = (const ulonglong2*)(Gs  + k * F + hoff);
#pragma unroll
        for (int q = 0; q < 4; q++) {
            ulonglong2 a = mr[q];
            o[2*q+0] = ffma2(xk2, a.x, o[2*q+0]);
            o[2*q+1] = ffma2(xk2, a.y, o[2*q+1]);
        }
#pragma unroll
        for (int q = 0; q < 4; q++) {
            ulonglong2 a = gr[q];
            tt[2*q+0] = ffma2(xk2, a.x, tt[2*q+0]);
            tt[2*q+1] = ffma2(xk2, a.y, tt[2*q+1]);
        }
    }

    // ---- diag partial: sum_f (tt[f]+v[f]) * x[f] over this half ----
    u64 dacc = 0ull;
#pragma unroll
    for (int i = 0; i < 8; i++) {
        u64 tv = add2(tt[i], ((const u64*)vs)[h * 8 + i]);
        dacc = ffma2(tv, xp[i], dacc);
    }
    float2 dd = up2(dacc);
    ds[h][r] = dd.x + dd.y;
    __syncthreads();

    const float diag = ds[0][r] + ds[1][r] + cs1;
    const float s = diag * INV_N;
    const u64 ns2 = pk2(-s, -s);

    // ---- residual + uw term + store ----
#pragma unroll
    for (int i = 0; i < 8; i++) o[i] = add2(o[i], xp[i]);

    const float* uwb = g_uwT + ((size_t)b * F + hoff) * NSEQ + row_in_b;
#pragma unroll
    for (int i = 0; i < 8; i++) {
        float a0 = uwb[(size_t)(2*i + 0) * NSEQ];
        float a1 = uwb[(size_t)(2*i + 1) * NSEQ];
        o[i] = ffma2(ns2, pk2(a0, a1), o[i]);
    }

    float* op = out + gx + hoff;
#pragma unroll
    for (int q = 0; q < 4; q++) {
        float2 lo = up2(o[2*q+0]), hi = up2(o[2*q+1]);
        ((float4*)op)[q] = make_float4(lo.x, lo.y, hi.x, hi.y);
    }
}

// ---------------------------------------------------------------------------
extern "C" void kernel_launch(void* const* d_in, const int* in_sizes, int n_in,
                              void* d_out, int out_size)
{
    const float* x     = (const float*)d_in[0];
    const float* w_psi = (const float*)d_in[1];
    const float* b_psi = (const float*)d_in[2];
    const float* w_phi = (const float*)d_in[3];
    const float* b_phi = (const float*)d_in[4];
    const float* w_u   = (const float*)d_in[5];
    const float* b_u   = (const float*)d_in[6];
    const float* w_r   = (const float*)d_in[7];
    float* out = (float*)d_out;

    k_pre<<<1, 256>>>(w_psi, b_psi, w_phi, b_phi);
    dim3 g1(BATCH, SPLITS);
    k1<<<g1, 128>>>(x, w_u, b_u, w_r);
    k_reduceM<<<BATCH, 256>>>(w_phi, b_phi, w_r, w_psi, b_psi);
    k_main<<<BATCH * 32, 128>>>(x, out);
}

// round 14
// speedup vs baseline: 1.1414x; 1.1414x over previous
#include <cuda_runtime.h>

typedef unsigned long long u64;

#define BATCH 32
#define NSEQ  2048
#define F     32
#define SPLITS 32
#define ROWS1 64
#define INV_N (1.0f / 2048.0f)

// Scratch (fully overwritten every launch -> deterministic)
__device__ float g_Spart[BATCH * SPLITS * F * F];   // xT @ u partials
__device__ float g_supart[BATCH * SPLITS * F];      // colsum(u) partials
__device__ float g_uwT[BATCH * F * NSEQ];           // (u @ w_r) transposed
__device__ float g_M3[BATCH * F * F];               // W_psi @ (M @ w_r * invN)
__device__ float g_b3[BATCH * F];                   // b_psi @ (M @ w_r * invN)
__device__ float g_G[F * F];                        // W_psi @ W_phi^T
__device__ float g_v[F];                            // W_psi@b_phi + W_phi@b_psi
__device__ float g_c[1];                            // b_psi . b_phi

// ---- packed f32x2 helpers ----
__device__ __forceinline__ u64 pk2(float a, float b) {
    u64 r; asm("mov.b64 %0,{%1,%2};" : "=l"(r) : "f"(a), "f"(b)); return r;
}
__device__ __forceinline__ float2 up2(u64 v) {
    float2 f; asm("mov.b64 {%0,%1},%2;" : "=f"(f.x), "=f"(f.y) : "l"(v)); return f;
}
__device__ __forceinline__ u64 ffma2(u64 a, u64 b, u64 c) {
    u64 d; asm("fma.rn.f32x2 %0,%1,%2,%3;" : "=l"(d) : "l"(a), "l"(b), "l"(c)); return d;
}
__device__ __forceinline__ u64 add2(u64 a, u64 b) {
    u64 d; asm("add.rn.f32x2 %0,%1,%2;" : "=l"(d) : "l"(a), "l"(b)); return d;
}

// ---------------------------------------------------------------------------
// k1 (unchanged from R13): per 64-row slice (2 thr/row, 16 feats):
//   u = relu(x@Wu + bu); uw = u@w_r (persist transposed);
//   S_part = x^T @ u; su_part = colsum(u).
// ---------------------------------------------------------------------------
__global__ __launch_bounds__(128) void k1(
    const float* __restrict__ x,
    const float* __restrict__ w_u, const float* __restrict__ b_u,
    const float* __restrict__ w_r)
{
    __shared__ alignas(16) float ws_u[F * F], ws_r[F * F];
    __shared__ alignas(16) float bs_u[F];
    __shared__ alignas(16) float x36[ROWS1 * 36];
    __shared__ alignas(16) float u33[ROWS1 * 33];

    const int b     = blockIdx.x;
    const int split = blockIdx.y;
    const int t     = threadIdx.x;
    const int r     = t & 63;
    const int h     = t >> 6;
    const int lane  = t & 31;
    const int w     = t >> 5;
    const int hoff  = h * 16;

#pragma unroll
    for (int i = t; i < 256; i += 128) {
        ((float4*)ws_u)[i] = ((const float4*)w_u)[i];
        ((float4*)ws_r)[i] = ((const float4*)w_r)[i];
    }
    if (t < F) bs_u[t] = b_u[t];

    const int row_in_b = split * ROWS1 + r;
    const float* xrow = x + ((size_t)b * NSEQ + row_in_b) * F;

    float xv[F];
#pragma unroll
    for (int i = 0; i < 8; i++) {
        float4 v = ((const float4*)xrow)[i];
        xv[4*i+0] = v.x; xv[4*i+1] = v.y; xv[4*i+2] = v.z; xv[4*i+3] = v.w;
    }
    u64 xp[8];
#pragma unroll
    for (int i = 0; i < 8; i++) xp[i] = ((const u64*)(xrow + hoff))[i];
    __syncthreads();

    // ---- u = relu(x@Wu + bu), 16 feats ----
    u64 uv[8];
#pragma unroll
    for (int i = 0; i < 8; i++) uv[i] = ((const u64*)bs_u)[h * 8 + i];
#pragma unroll
    for (int k = 0; k < F; k++) {
        const u64 xk2 = pk2(xv[k], xv[k]);
        const ulonglong2* wu = (const ulonglong2*)(ws_u + k * F + hoff);
#pragma unroll
        for (int q = 0; q < 4; q++) {
            ulonglong2 a = wu[q];
            uv[2*q+0] = ffma2(xk2, a.x, uv[2*q+0]);
            uv[2*q+1] = ffma2(xk2, a.y, uv[2*q+1]);
        }
    }
#pragma unroll
    for (int i = 0; i < 8; i++) {
        float2 tu = up2(uv[i]);
        uv[i] = pk2(fmaxf(tu.x, 0.0f), fmaxf(tu.y, 0.0f));
    }

    // ---- stage u (stride 33) and x (stride 36) ----
#pragma unroll
    for (int i = 0; i < 8; i++) {
        float2 tu = up2(uv[i]);
        u33[r * 33 + hoff + 2*i + 0] = tu.x;
        u33[r * 33 + hoff + 2*i + 1] = tu.y;
    }
#pragma unroll
    for (int q = 0; q < 4; q++) {
        ulonglong2 v; v.x = xp[2*q]; v.y = xp[2*q+1];
        ((ulonglong2*)(x36 + r * 36 + hoff))[q] = v;
    }
    __syncthreads();

    // ---- uw = u @ w_r (16 feats), persist transposed ----
    u64 uw[8] = {0,0,0,0,0,0,0,0};
#pragma unroll
    for (int f = 0; f < F; f++) {
        const float uf = u33[r * 33 + f];
        const u64 uf2 = pk2(uf, uf);
        const ulonglong2* wr = (const ulonglong2*)(ws_r + f * F + hoff);
#pragma unroll
        for (int q = 0; q < 4; q++) {
            ulonglong2 a = wr[q];
            uw[2*q+0] = ffma2(uf2, a.x, uw[2*q+0]);
            uw[2*q+1] = ffma2(uf2, a.y, uw[2*q+1]);
        }
    }
#pragma unroll
    for (int i = 0; i < 8; i++) {
        float2 v = up2(uw[i]);
        g_uwT[((size_t)b * F + hoff + 2*i + 0) * NSEQ + row_in_b] = v.x;
        g_uwT[((size_t)b * F + hoff + 2*i + 1) * NSEQ + row_in_b] = v.y;
    }

    // ---- S_part[k][f2] = sum_j x[j][k]*u[j][f2]; su_part = colsum(u) ----
    u64 acc2[4] = {0,0,0,0};
    float susum = 0.0f;
#pragma unroll 4
    for (int j = 0; j < ROWS1; j++) {
        const float uj = u33[j * 33 + lane];
        const u64 uj2 = pk2(uj, uj);
        const ulonglong2* xr2 = (const ulonglong2*)(x36 + j * 36 + w * 8);
        ulonglong2 p0 = xr2[0], p1 = xr2[1];
        acc2[0] = ffma2(uj2, p0.x, acc2[0]);
        acc2[1] = ffma2(uj2, p0.y, acc2[1]);
        acc2[2] = ffma2(uj2, p1.x, acc2[2]);
        acc2[3] = ffma2(uj2, p1.y, acc2[3]);
        susum += uj;
    }
    float* sp = g_Spart + ((size_t)(b * SPLITS + split)) * F * F;
#pragma unroll
    for (int q = 0; q < 4; q++) {
        float2 v = up2(acc2[q]);
        sp[(8*w + 2*q + 0) * F + lane] = v.x;
        sp[(8*w + 2*q + 1) * F + lane] = v.y;
    }
    if (w == 0)
        g_supart[(b * SPLITS + split) * F + lane] = susum;
}

// ---------------------------------------------------------------------------
// k_reduceM (+ folded k_pre): all blocks also write identical G/v/c.
// S = sum partials; M = Wphi^T S + bphi (x) su; M2 = M@wr*invN;
// M3 = Wpsi@M2; b3 = bpsi@M2.
// ---------------------------------------------------------------------------
__global__ __launch_bounds__(256) void k_reduceM(
    const float* __restrict__ w_phi, const float* __restrict__ b_phi,
    const float* __restrict__ w_r,
    const float* __restrict__ w_psi, const float* __restrict__ b_psi)
{
    __shared__ alignas(16) float Ss[F * F], wfs[F * F], wrs[F * F], wps[F * F];
    __shared__ alignas(16) float Ms[F * F], m2s[F * F];
    __shared__ alignas(16) float sus[F], bfs[F], bps[F];
    const int b = blockIdx.x;
    const int t = threadIdx.x;

#pragma unroll
    for (int e = t; e < F * F; e += 256) {
        float s = 0.0f;
        const float* sp = g_Spart + (size_t)b * SPLITS * F * F + e;
#pragma unroll
        for (int q = 0; q < SPLITS; q++) s += sp[q * F * F];
        Ss[e]  = s;
        wfs[e] = w_phi[e];
        wrs[e] = w_r[e];
        wps[e] = w_psi[e];
    }
    if (t < F) {
        float s = 0.0f;
        const float* up = g_supart + (size_t)b * SPLITS * F + t;
#pragma unroll
        for (int q = 0; q < SPLITS; q++) s += up[q * F];
        sus[t] = s;
        bfs[t] = b_phi[t];
        bps[t] = b_psi[t];
    }
    __syncthreads();

    const int f1 = t >> 3;
    const int c0 = (t & 7) * 4;

    // folded k_pre: G, v, c (identical values from every block -> benign)
    {
        float a0 = 0.f, a1 = 0.f, a2 = 0.f, a3 = 0.f;
#pragma unroll
        for (int f = 0; f < F; f++) {
            const float pw = wps[f1 * F + f];
            a0 += pw * wfs[(c0 + 0) * F + f];
            a1 += pw * wfs[(c0 + 1) * F + f];
            a2 += pw * wfs[(c0 + 2) * F + f];
            a3 += pw * wfs[(c0 + 3) * F + f];
        }
        *(float4*)(g_G + f1 * F + c0) = make_float4(a0, a1, a2, a3);
    }
    if (t < F) {
        float s = 0.f;
#pragma unroll
        for (int f = 0; f < F; f++)
            s += wps[t * F + f] * bfs[f] + wfs[t * F + f] * bps[f];
        g_v[t] = s;
    }
    if (t == 0) {
        float s = 0.f;
#pragma unroll
        for (int f = 0; f < F; f++) s += bps[f] * bfs[f];
        g_c[0] = s;
    }

    {   // M[f1][c0..] = sum_m Wphi[m][f1]*S[m][c0..] + bphi[f1]*su[c0..]
        float4 su4 = *(const float4*)(sus + c0);
        const float bf = bfs[f1];
        float a0 = bf * su4.x, a1 = bf * su4.y, a2 = bf * su4.z, a3 = bf * su4.w;
#pragma unroll
        for (int m = 0; m < F; m++) {
            const float wv = wfs[m * F + f1];
            float4 s4 = *(const float4*)(Ss + m * F + c0);
            a0 += wv * s4.x; a1 += wv * s4.y; a2 += wv * s4.z; a3 += wv * s4.w;
        }
        *(float4*)(Ms + f1 * F + c0) = make_float4(a0, a1, a2, a3);
    }
    __syncthreads();
    {   // M2 = M @ wr * invN
        float a0 = 0.f, a1 = 0.f, a2 = 0.f, a3 = 0.f;
#pragma unroll
        for (int m = 0; m < F; m++) {
            const float mv = Ms[f1 * F + m];
            float4 w4 = *(const float4*)(wrs + m * F + c0);
            a0 += mv * w4.x; a1 += mv * w4.y; a2 += mv * w4.z; a3 += mv * w4.w;
        }
        *(float4*)(m2s + f1 * F + c0) =
            make_float4(a0 * INV_N, a1 * INV_N, a2 * INV_N, a3 * INV_N);
    }
    __syncthreads();
    {   // M3 = Wpsi @ M2
        float a0 = 0.f, a1 = 0.f, a2 = 0.f, a3 = 0.f;
#pragma unroll
        for (int m = 0; m < F; m++) {
            const float wv = wps[f1 * F + m];
            float4 m4 = *(const float4*)(m2s + m * F + c0);
            a0 += wv * m4.x; a1 += wv * m4.y; a2 += wv * m4.z; a3 += wv * m4.w;
        }
        *(float4*)(g_M3 + (size_t)b * F * F + f1 * F + c0) =
            make_float4(a0, a1, a2, a3);
    }
    if (t < 8) {   // b3 = bpsi @ M2
        const int f = t * 4;
        float a0 = 0.f, a1 = 0.f, a2 = 0.f, a3 = 0.f;
#pragma unroll
        for (int m = 0; m < F; m++) {
            const float bv = bps[m];
            float4 m4 = *(const float4*)(m2s + m * F + f);
            a0 += bv * m4.x; a1 += bv * m4.y; a2 += bv * m4.z; a3 += bv * m4.w;
        }
        *(float4*)(g_b3 + (size_t)b * F + f) = make_float4(a0, a1, a2, a3);
    }
}

// ---------------------------------------------------------------------------
// k_main (NEW): 4 thr/row, 32 rows/block, 2048 blocks.
// warp = 8 rows x 4 feature-quarters (lane = qq*8 + rr).
// x from stride-34 smem tile; uw prefetched before main loop;
// diag reduced with 2x shfl_xor; single __syncthreads.
//   out = x + x@M3 + b3 - ((x@G.x + x.v + c)/N) * uw
// ---------------------------------------------------------------------------
__global__ __launch_bounds__(128) void k_main(
    const float* __restrict__ x, float* __restrict__ out)
{
    __shared__ alignas(16) float Gs[F * F], m3s[F * F];
    __shared__ alignas(16) float vs[F], b3s[F];
    __shared__ alignas(16) float x34[32 * 34];
    __shared__ float cs1;

    const int b     = blockIdx.x >> 6;          // 64 chunks of 32 rows
    const int chunk = blockIdx.x & 63;
    const int t     = threadIdx.x;
    const int w     = t >> 5;
    const int lane  = t & 31;
    const int qq    = lane >> 3;                // feature quarter
    const int rr    = lane & 7;
    const int r     = w * 8 + rr;               // local row 0..31
    const int hoff  = qq * 8;

#pragma unroll
    for (int i = t; i < 256; i += 128) {
        ((float4*)Gs )[i] = ((const float4*)g_G)[i];
        ((float4*)m3s)[i] = ((const float4*)(g_M3 + (size_t)b * F * F))[i];
    }
    if (t < F) { vs[t] = g_v[t]; b3s[t] = g_b3[(size_t)b * F + t]; }
    if (t == 0) cs1 = g_c[0];

    const int base = chunk * 32;
    {   // stage x tile 32x32 -> stride 34 (conflict-free both orientations)
        const float* xg = x + ((size_t)b * NSEQ + base) * F;
#pragma unroll
        for (int i = t; i < 256; i += 128) {
            int row = i >> 3, c = (i & 7) << 2;
            float4 v = ((const float4*)xg)[i];
            float* dst = x34 + row * 34 + c;
            dst[0] = v.x; dst[1] = v.y; dst[2] = v.z; dst[3] = v.w;
        }
    }

    // prefetch uw early (latency overlaps the main loop)
    const int myrow = base + r;
    float uwv[8];
    {
        const float* uwb = g_uwT + ((size_t)b * F + hoff) * NSEQ + myrow;
#pragma unroll
        for (int i = 0; i < 8; i++) uwv[i] = uwb[(size_t)i * NSEQ];
    }
    __syncthreads();

    // own 8 features of x, packed (stride 34 even -> 8B aligned)
    u64 xp[4];
#pragma unroll
    for (int i = 0; i < 4; i++) xp[i] = ((const u64*)(x34 + r * 34 + hoff))[i];

    // fused loop: o = b3 + x@M3 ; tt = x@G  (8 feats each)
    u64 o[4], tt[4];
#pragma unroll
    for (int i = 0; i < 4; i++) { o[i] = ((const u64*)b3s)[qq * 4 + i]; tt[i] = 0ull; }
#pragma unroll
    for (int k = 0; k < F; k++) {
        const float xk = x34[r * 34 + k];
        const u64 xk2 = pk2(xk, xk);
        const ulonglong2* mr = (const ulonglong2*)(m3s + k * F + hoff);
        const ulonglong2* gr = (const ulonglong2*)(Gs  + k * F + hoff);
        ulonglong2 a0 = mr[0], a1 = mr[1];
        o[0] = ffma2(xk2, a0.x, o[0]); o[1] = ffma2(xk2, a0.y, o[1]);
        o[2] = ffma2(xk2, a1.x, o[2]); o[3] = ffma2(xk2, a1.y, o[3]);
        ulonglong2 g0 = gr[0], g1 = gr[1];
        tt[0] = ffma2(xk2, g0.x, tt[0]); tt[1] = ffma2(xk2, g0.y, tt[1]);
        tt[2] = ffma2(xk2, g1.x, tt[2]); tt[3] = ffma2(xk2, g1.y, tt[3]);
    }

    // diag partial over own 8 feats, then butterfly across the 4 quarters
    u64 dacc = 0ull;
#pragma unroll
    for (int i = 0; i < 4; i++) {
        u64 tv = add2(tt[i], ((const u64*)vs)[qq * 4 + i]);
        dacc = ffma2(tv, xp[i], dacc);
    }
    float2 dd = up2(dacc);
    float d = dd.x + dd.y;
    d += __shfl_xor_sync(0xffffffffu, d, 8);
    d += __shfl_xor_sync(0xffffffffu, d, 16);
    const float s = (d + cs1) * INV_N;
    const u64 ns2 = pk2(-s, -s);

    // out = x + o - s*uw
#pragma unroll
    for (int i = 0; i < 4; i++) {
        o[i] = add2(o[i], xp[i]);
        o[i] = ffma2(ns2, pk2(uwv[2*i + 0], uwv[2*i + 1]), o[i]);
    }

    float* op = out + ((size_t)b * NSEQ + myrow) * F + hoff;
#pragma unroll
    for (int q = 0; q < 2; q++) {
        float2 lo = up2(o[2*q+0]), hi = up2(o[2*q+1]);
        ((float4*)op)[q] = make_float4(lo.x, lo.y, hi.x, hi.y);
    }
}

// ---------------------------------------------------------------------------
extern "C" void kernel_launch(void* const* d_in, const int* in_sizes, int n_in,
                              void* d_out, int out_size)
{
    const float* x     = (const float*)d_in[0];
    const float* w_psi = (const float*)d_in[1];
    const float* b_psi = (const float*)d_in[2];
    const float* w_phi = (const float*)d_in[3];
    const float* b_phi = (const float*)d_in[4];
    const float* w_u   = (const float*)d_in[5];
    const float* b_u   = (const float*)d_in[6];
    const float* w_r   = (const float*)d_in[7];
    float* out = (float*)d_out;

    dim3 g1(BATCH, SPLITS);
    k1<<<g1, 128>>>(x, w_u, b_u, w_r);
    k_reduceM<<<BATCH, 256>>>(w_phi, b_phi, w_r, w_psi, b_psi);
    k_main<<<BATCH * 64, 128>>>(x, out);
}

// round 16
// speedup vs baseline: 1.2102x; 1.0602x over previous
#include <cuda_runtime.h>

typedef unsigned long long u64;

#define BATCH 32
#define NSEQ  2048
#define F     32
#define SPLITS1 64              // k1 splits (32 rows each)
#define ROWS1 32
#define INV_N (1.0f / 2048.0f)

// Scratch (fully overwritten every launch -> deterministic)
__device__ float g_Spart[BATCH * SPLITS1 * F * F];  // xT @ u partials
__device__ float g_supart[BATCH * SPLITS1 * F];     // colsum(u) partials
__device__ float g_uwT[BATCH * F * NSEQ];           // (u @ w_r) transposed
__device__ float g_M3[BATCH * F * F];               // W_psi @ (M @ w_r * invN)
__device__ float g_b3[BATCH * F];                   // b_psi @ (M @ w_r * invN)
__device__ float g_G[F * F];                        // W_psi @ W_phi^T
__device__ float g_v[F];                            // W_psi@b_phi + W_phi@b_psi
__device__ float g_c[1];                            // b_psi . b_phi

// ---- packed f32x2 helpers ----
__device__ __forceinline__ u64 pk2(float a, float b) {
    u64 r; asm("mov.b64 %0,{%1,%2};" : "=l"(r) : "f"(a), "f"(b)); return r;
}
__device__ __forceinline__ float2 up2(u64 v) {
    float2 f; asm("mov.b64 {%0,%1},%2;" : "=f"(f.x), "=f"(f.y) : "l"(v)); return f;
}
__device__ __forceinline__ u64 ffma2(u64 a, u64 b, u64 c) {
    u64 d; asm("fma.rn.f32x2 %0,%1,%2,%3;" : "=l"(d) : "l"(a), "l"(b), "l"(c)); return d;
}
__device__ __forceinline__ u64 add2(u64 a, u64 b) {
    u64 d; asm("add.rn.f32x2 %0,%1,%2;" : "=l"(d) : "l"(a), "l"(b)); return d;
}

// ---------------------------------------------------------------------------
// k1: 32 rows/block, 2048 blocks. warp = 8 rows x 4 feature-quarters.
//   x tile stride 36 (16B-aligned .128 phase-B reads); u tile stride 34.
//   u = relu(x@Wu + bu) (8 feats/thr); uw = u@w_r -> g_uwT;
//   S_part = x^T u; su_part = colsum(u).
// ---------------------------------------------------------------------------
__global__ __launch_bounds__(128) void k1(
    const float* __restrict__ x,
    const float* __restrict__ w_u, const float* __restrict__ b_u,
    const float* __restrict__ w_r)
{
    __shared__ alignas(16) float ws_u[F * F], ws_r[F * F];
    __shared__ alignas(16) float bs_u[F];
    __shared__ alignas(16) float x36[ROWS1 * 36];   // stride 36: .128-aligned
    __shared__ alignas(16) float u34[ROWS1 * 34];

    const int b     = blockIdx.x;
    const int split = blockIdx.y;
    const int t     = threadIdx.x;
    const int w     = t >> 5;
    const int lane  = t & 31;
    const int qq    = lane >> 3;
    const int rr    = lane & 7;
    const int r     = w * 8 + rr;            // local row 0..31
    const int hoff  = qq * 8;

#pragma unroll
    for (int i = t; i < 256; i += 128) {
        ((float4*)ws_u)[i] = ((const float4*)w_u)[i];
        ((float4*)ws_r)[i] = ((const float4*)w_r)[i];
    }
    if (t < F) bs_u[t] = b_u[t];

    const int base = split * ROWS1;
    {   // stage x tile (32x32 -> stride 36, float4 aligned)
        const float* xg = x + ((size_t)b * NSEQ + base) * F;
#pragma unroll
        for (int i = t; i < 256; i += 128) {
            int row = i >> 3, c = (i & 7) << 2;
            float4 v = ((const float4*)xg)[i];
            *(float4*)(x36 + row * 36 + c) = v;   // 36*row + c ≡ 0 mod 4
        }
    }
    __syncthreads();

    // ---- u = relu(bu + x@Wu), 8 feats ----
    u64 uv[4];
#pragma unroll
    for (int i = 0; i < 4; i++) uv[i] = ((const u64*)bs_u)[qq * 4 + i];
#pragma unroll
    for (int k = 0; k < F; k++) {
        const float xk = x36[r * 36 + k];          // bcast, conflict-free
        const u64 xk2 = pk2(xk, xk);
        const ulonglong2* wu = (const ulonglong2*)(ws_u + k * F + hoff);
        ulonglong2 a0 = wu[0], a1 = wu[1];
        uv[0] = ffma2(xk2, a0.x, uv[0]); uv[1] = ffma2(xk2, a0.y, uv[1]);
        uv[2] = ffma2(xk2, a1.x, uv[2]); uv[3] = ffma2(xk2, a1.y, uv[3]);
    }
#pragma unroll
    for (int i = 0; i < 4; i++) {
        float2 tu = up2(uv[i]);
        uv[i] = pk2(fmaxf(tu.x, 0.0f), fmaxf(tu.y, 0.0f));
    }
    // stage u (stride 34; r*34+hoff even -> 8B aligned u64 stores)
#pragma unroll
    for (int i = 0; i < 4; i++)
        ((u64*)(u34 + r * 34 + hoff))[i] = uv[i];
    __syncthreads();

    // ---- uw = u @ w_r (8 feats), persist transposed ----
    const int grow = base + r;
    u64 uw[4] = {0,0,0,0};
#pragma unroll
    for (int f = 0; f < F; f++) {
        const float uf = u34[r * 34 + f];          // bcast
        const u64 uf2 = pk2(uf, uf);
        const ulonglong2* wr = (const ulonglong2*)(ws_r + f * F + hoff);
        ulonglong2 a0 = wr[0], a1 = wr[1];
        uw[0] = ffma2(uf2, a0.x, uw[0]); uw[1] = ffma2(uf2, a0.y, uw[1]);
        uw[2] = ffma2(uf2, a1.x, uw[2]); uw[3] = ffma2(uf2, a1.y, uw[3]);
    }
#pragma unroll
    for (int i = 0; i < 4; i++) {
        float2 v = up2(uw[i]);
        g_uwT[((size_t)b * F + hoff + 2*i + 0) * NSEQ + grow] = v.x;
        g_uwT[((size_t)b * F + hoff + 2*i + 1) * NSEQ + grow] = v.y;
    }

    // ---- S_part[k][f2] = sum_j x[j][k]*u[j][f2]; su_part = colsum(u) ----
    u64 acc2[4] = {0,0,0,0};
    float susum = 0.0f;
#pragma unroll 4
    for (int j = 0; j < ROWS1; j++) {
        const float uj = u34[j * 34 + lane];       // lane-strided conflict-free
        const u64 uj2 = pk2(uj, uj);
        const ulonglong2* xr2 = (const ulonglong2*)(x36 + j * 36 + w * 8);
        ulonglong2 p0 = xr2[0], p1 = xr2[1];       // uniform .128, 16B aligned
        acc2[0] = ffma2(uj2, p0.x, acc2[0]);
        acc2[1] = ffma2(uj2, p0.y, acc2[1]);
        acc2[2] = ffma2(uj2, p1.x, acc2[2]);
        acc2[3] = ffma2(uj2, p1.y, acc2[3]);
        susum += uj;
    }
    float* sp = g_Spart + ((size_t)(b * SPLITS1 + split)) * F * F;
#pragma unroll
    for (int q = 0; q < 4; q++) {
        float2 v = up2(acc2[q]);
        sp[(8*w + 2*q + 0) * F + lane] = v.x;
        sp[(8*w + 2*q + 1) * F + lane] = v.y;
    }
    if (w == 0)
        g_supart[(b * SPLITS1 + split) * F + lane] = susum;
}

// ---------------------------------------------------------------------------
// k_reduceM (+ folded k_pre): S = sum partials; M = Wphi^T S + bphi (x) su;
// M2 = M@wr*invN; M3 = Wpsi@M2; b3 = bpsi@M2; G/v/c (identical per block).
// ---------------------------------------------------------------------------
__global__ __launch_bounds__(256) void k_reduceM(
    const float* __restrict__ w_phi, const float* __restrict__ b_phi,
    const float* __restrict__ w_r,
    const float* __restrict__ w_psi, const float* __restrict__ b_psi)
{
    __shared__ alignas(16) float Ss[F * F], wfs[F * F], wrs[F * F], wps[F * F];
    __shared__ alignas(16) float Ms[F * F], m2s[F * F];
    __shared__ alignas(16) float sus[F], bfs[F], bps[F];
    const int b = blockIdx.x;
    const int t = threadIdx.x;

#pragma unroll
    for (int e = t; e < F * F; e += 256) {
        float s = 0.0f;
        const float* sp = g_Spart + (size_t)b * SPLITS1 * F * F + e;
#pragma unroll
        for (int q = 0; q < SPLITS1; q++) s += sp[q * F * F];
        Ss[e]  = s;
        wfs[e] = w_phi[e];
        wrs[e] = w_r[e];
        wps[e] = w_psi[e];
    }
    if (t < F) {
        float s = 0.0f;
        const float* up = g_supart + (size_t)b * SPLITS1 * F + t;
#pragma unroll
        for (int q = 0; q < SPLITS1; q++) s += up[q * F];
        sus[t] = s;
        bfs[t] = b_phi[t];
        bps[t] = b_psi[t];
    }
    __syncthreads();

    const int f1 = t >> 3;
    const int c0 = (t & 7) * 4;

    // folded k_pre: G, v, c (identical values from every block -> benign)
    {
        float a0 = 0.f, a1 = 0.f, a2 = 0.f, a3 = 0.f;
#pragma unroll
        for (int f = 0; f < F; f++) {
            const float pw = wps[f1 * F + f];
            a0 += pw * wfs[(c0 + 0) * F + f];
            a1 += pw * wfs[(c0 + 1) * F + f];
            a2 += pw * wfs[(c0 + 2) * F + f];
            a3 += pw * wfs[(c0 + 3) * F + f];
        }
        *(float4*)(g_G + f1 * F + c0) = make_float4(a0, a1, a2, a3);
    }
    if (t < F) {
        float s = 0.f;
#pragma unroll
        for (int f = 0; f < F; f++)
            s += wps[t * F + f] * bfs[f] + wfs[t * F + f] * bps[f];
        g_v[t] = s;
    }
    if (t == 0) {
        float s = 0.f;
#pragma unroll
        for (int f = 0; f < F; f++) s += bps[f] * bfs[f];
        g_c[0] = s;
    }

    {   // M[f1][c0..] = sum_m Wphi[m][f1]*S[m][c0..] + bphi[f1]*su[c0..]
        float4 su4 = *(const float4*)(sus + c0);
        const float bf = bfs[f1];
        float a0 = bf * su4.x, a1 = bf * su4.y, a2 = bf * su4.z, a3 = bf * su4.w;
#pragma unroll
        for (int m = 0; m < F; m++) {
            const float wv = wfs[m * F + f1];
            float4 s4 = *(const float4*)(Ss + m * F + c0);
            a0 += wv * s4.x; a1 += wv * s4.y; a2 += wv * s4.z; a3 += wv * s4.w;
        }
        *(float4*)(Ms + f1 * F + c0) = make_float4(a0, a1, a2, a3);
    }
    __syncthreads();
    {   // M2 = M @ wr * invN
        float a0 = 0.f, a1 = 0.f, a2 = 0.f, a3 = 0.f;
#pragma unroll
        for (int m = 0; m < F; m++) {
            const float mv = Ms[f1 * F + m];
            float4 w4 = *(const float4*)(wrs + m * F + c0);
            a0 += mv * w4.x; a1 += mv * w4.y; a2 += mv * w4.z; a3 += mv * w4.w;
        }
        *(float4*)(m2s + f1 * F + c0) =
            make_float4(a0 * INV_N, a1 * INV_N, a2 * INV_N, a3 * INV_N);
    }
    __syncthreads();
    {   // M3 = Wpsi @ M2
        float a0 = 0.f, a1 = 0.f, a2 = 0.f, a3 = 0.f;
#pragma unroll
        for (int m = 0; m < F; m++) {
            const float wv = wps[f1 * F + m];
            float4 m4 = *(const float4*)(m2s + m * F + c0);
            a0 += wv * m4.x; a1 += wv * m4.y; a2 += wv * m4.z; a3 += wv * m4.w;
        }
        *(float4*)(g_M3 + (size_t)b * F * F + f1 * F + c0) =
            make_float4(a0, a1, a2, a3);
    }
    if (t < 8) {   // b3 = bpsi @ M2
        const int f = t * 4;
        float a0 = 0.f, a1 = 0.f, a2 = 0.f, a3 = 0.f;
#pragma unroll
        for (int m = 0; m < F; m++) {
            const float bv = bps[m];
            float4 m4 = *(const float4*)(m2s + m * F + f);
            a0 += bv * m4.x; a1 += bv * m4.y; a2 += bv * m4.z; a3 += bv * m4.w;
        }
        *(float4*)(g_b3 + (size_t)b * F + f) = make_float4(a0, a1, a2, a3);
    }
}

// ---------------------------------------------------------------------------
// k_main (unchanged R14 winner): 4 thr/row, 32 rows/block, 2048 blocks.
//   out = x + x@M3 + b3 - ((x@G.x + x.v + c)/N) * uw
// ---------------------------------------------------------------------------
__global__ __launch_bounds__(128) void k_main(
    const float* __restrict__ x, float* __restrict__ out)
{
    __shared__ alignas(16) float Gs[F * F], m3s[F * F];
    __shared__ alignas(16) float vs[F], b3s[F];
    __shared__ alignas(16) float x34[32 * 34];
    __shared__ float cs1;

    const int b     = blockIdx.x >> 6;
    const int chunk = blockIdx.x & 63;
    const int t     = threadIdx.x;
    const int w     = t >> 5;
    const int lane  = t & 31;
    const int qq    = lane >> 3;
    const int rr    = lane & 7;
    const int r     = w * 8 + rr;
    const int hoff  = qq * 8;

#pragma unroll
    for (int i = t; i < 256; i += 128) {
        ((float4*)Gs )[i] = ((const float4*)g_G)[i];
        ((float4*)m3s)[i] = ((const float4*)(g_M3 + (size_t)b * F * F))[i];
    }
    if (t < F) { vs[t] = g_v[t]; b3s[t] = g_b3[(size_t)b * F + t]; }
    if (t == 0) cs1 = g_c[0];

    const int base = chunk * 32;
    {
        const float* xg = x + ((size_t)b * NSEQ + base) * F;
#pragma unroll
        for (int i = t; i < 256; i += 128) {
            int row = i >> 3, c = (i & 7) << 2;
            float4 v = ((const float4*)xg)[i];
            float* dst = x34 + row * 34 + c;     // scalar stores (alignment-safe)
            dst[0] = v.x; dst[1] = v.y; dst[2] = v.z; dst[3] = v.w;
        }
    }

    const int myrow = base + r;
    float uwv[8];
    {
        const float* uwb = g_uwT + ((size_t)b * F + hoff) * NSEQ + myrow;
#pragma unroll
        for (int i = 0; i < 8; i++) uwv[i] = uwb[(size_t)i * NSEQ];
    }
    __syncthreads();

    u64 xp[4];
#pragma unroll
    for (int i = 0; i < 4; i++) xp[i] = ((const u64*)(x34 + r * 34 + hoff))[i];

    u64 o[4], tt[4];
#pragma unroll
    for (int i = 0; i < 4; i++) { o[i] = ((const u64*)b3s)[qq * 4 + i]; tt[i] = 0ull; }
#pragma unroll
    for (int k = 0; k < F; k++) {
        const float xk = x34[r * 34 + k];
        const u64 xk2 = pk2(xk, xk);
        const ulonglong2* mr = (const ulonglong2*)(m3s + k * F + hoff);
        const ulonglong2* gr = (const ulonglong2*)(Gs  + k * F + hoff);
        ulonglong2 a0 = mr[0], a1 = mr[1];
        o[0] = ffma2(xk2, a0.x, o[0]); o[1] = ffma2(xk2, a0.y, o[1]);
        o[2] = ffma2(xk2, a1.x, o[2]); o[3] = ffma2(xk2, a1.y, o[3]);
        ulonglong2 g0 = gr[0], g1 = gr[1];
        tt[0] = ffma2(xk2, g0.x, tt[0]); tt[1] = ffma2(xk2, g0.y, tt[1]);
        tt[2] = ffma2(xk2, g1.x, tt[2]); tt[3] = ffma2(xk2, g1.y, tt[3]);
    }

    u64 dacc = 0ull;
#pragma unroll
    for (int i = 0; i < 4; i++) {
        u64 tv = add2(tt[i], ((const u64*)vs)[qq * 4 + i]);
        dacc = ffma2(tv, xp[i], dacc);
    }
    float2 dd = up2(dacc);
    float d = dd.x + dd.y;
    d += __shfl_xor_sync(0xffffffffu, d, 8);
    d += __shfl_xor_sync(0xffffffffu, d, 16);
    const float s = (d + cs1) * INV_N;
    const u64 ns2 = pk2(-s, -s);

#pragma unroll
    for (int i = 0; i < 4; i++) {
        o[i] = add2(o[i], xp[i]);
        o[i] = ffma2(ns2, pk2(uwv[2*i + 0], uwv[2*i + 1]), o[i]);
    }

    float* op = out + ((size_t)b * NSEQ + myrow) * F + hoff;
#pragma unroll
    for (int q = 0; q < 2; q++) {
        float2 lo = up2(o[2*q+0]), hi = up2(o[2*q+1]);
        ((float4*)op)[q] = make_float4(lo.x, lo.y, hi.x, hi.y);
    }
}

// ---------------------------------------------------------------------------
extern "C" void kernel_launch(void* const* d_in, const int* in_sizes, int n_in,
                              void* d_out, int out_size)
{
    const float* x     = (const float*)d_in[0];
    const float* w_psi = (const float*)d_in[1];
    const float* b_psi = (const float*)d_in[2];
    const float* w_phi = (const float*)d_in[3];
    const float* b_phi = (const float*)d_in[4];
    const float* w_u   = (const float*)d_in[5];
    const float* b_u   = (const float*)d_in[6];
    const float* w_r   = (const float*)d_in[7];
    float* out = (float*)d_out;

    dim3 g1(BATCH, SPLITS1);
    k1<<<g1, 128>>>(x, w_u, b_u, w_r);
    k_reduceM<<<BATCH, 256>>>(w_phi, b_phi, w_r, w_psi, b_psi);
    k_main<<<BATCH * 64, 128>>>(x, out);
}